// round 15
// baseline (speedup 1.0000x reference)
#include <cuda_runtime.h>

// BWSGODE: 8192-step serial scalar ODE — issue-bound single-thread loop.
//
// v15 = v14 (best, 101.3us) + final residue sweep:
//   - CHUNK 1024 -> 2048 (publishes 8 -> 4)
//   - consumer poll sleep 256 -> 1024ns (consumers have ~26us slack/chunk;
//     coarser napping cuts cross-SMSP scheduler traffic)
//   - producer prologue: all 15 input loads issued back-to-back (MLP=15,
//     single latency wave) before any dependent math
// Certified model (r12-r14): 12 fma-port multiplies x rt2 = 24 cyc/iter
// floor; measured 24.2. The 12 products are irreducible (each carries a
// runtime operand; all sharing rewrites add multiplies). fp64 offload and
// two-SMSP splitting are latency-dead (chain slack 8 cyc vs +80/+35).
// Structure (locked r7): thread 0 produces into shared traj, publishes
// chunks via fence + volatile store; warps 1,2,3,5,6,7 stream chunks to
// global as STG.128; warp 4 exits so SMSP 0 is producer-only.

#define CHUNK_LOG2 11
#define CHUNK (1 << CHUNK_LOG2)

__shared__ volatile int s_progress;

__global__ void __launch_bounds__(256, 1)
bwsg_ode_kernel(const float* __restrict__ y0,
                const float* __restrict__ p,
                float* __restrict__ out,
                int num_steps) {
    extern __shared__ float4 traj[];  // num_steps entries (128 KB @ 8192)

    const int tid = threadIdx.x;
    const int wid = tid >> 5;
    if (tid == 0) s_progress = 0;
    __syncthreads();  // the ONLY block-wide sync; everything after is P/C.

    const float iv = __ldg(&y0[4]);

    if (tid == 0) {
        // ---- producer prologue: one MLP-15 load wave ----
        float B = __ldg(&y0[0]);
        float W = __ldg(&y0[1]);
        float S = __ldg(&y0[2]);
        float G = __ldg(&y0[3]);
        const float q0 = __ldg(&p[0]);
        const float q1 = __ldg(&p[1]);
        const float q2 = __ldg(&p[2]);
        const float q3 = __ldg(&p[3]);
        const float q4 = __ldg(&p[4]);
        const float q5 = __ldg(&p[5]);
        const float q6 = __ldg(&p[6]);
        const float q7 = __ldg(&p[7]);
        const float q8 = __ldg(&p[8]);
        const float q9 = __ldg(&p[9]);

        const float p0 = q0, p2 = q2, p5 = q5, p8 = q8;
        const float np1 = -q1, np3 = -q3, np4 = -q4;
        const float np6 = -q6, np7 = -q7, np9 = -q9;
        const float np0 = -p0;

        const float fi  = (iv != 0.0f) ? 1.0f : 0.0f;
        const float thr = __fsub_rn(__fadd_rn(5.0f, iv), 1.0f);

        // First integer step with mask==1 (j >= thr <=> j >= ceil(thr) for
        // integer j; fp compare of exact integers is exact).
        int j0 = 1;
        if (fi != 0.0f) {
            float ct = ceilf(thr);
            if (ct > 1.0f) {
                j0 = (ct >= (float)num_steps) ? num_steps : (int)ct;
            }
        }

        traj[0] = make_float4(B, W, S, G);

        // ---- Phase 1: mask == 0 (interventional only), B frozen ----
        for (int j = 1; j < j0; ++j) {
            float a = __fmaf_rn(np0, G, p0);
            a       = __fmaf_rn(np1, S, a);
            float c = __fmaf_rn(p2, G, np4);
            float b = __fmaf_rn(np3, W, c);
            float d = __fmaf_rn(p5, S, np7);
            float e = __fmul_rn(W, d);
            float nS = __fmaf_rn(b, S, S);
            float nW = __fmaf_rn(e, W, W);
            float nG = __fmaf_rn(a, G, G);
            W = nW; S = nS; G = nG;
            traj[j] = make_float4(B, W, S, G);
        }

        // ---- Phase 2: mask == 1 hot loop (12 fma-port + 2 alu ops) ----
        int j = j0;
        while (j < num_steps) {
            const int end = min((((j >> CHUNK_LOG2) + 1) << CHUNK_LOG2),
                                num_steps);
            #pragma unroll 128
            for (; j < end; ++j) {
                float a = __fmaf_rn(np0, G, p0);     // p0 - p0*G
                a       = __fmaf_rn(np1, S, a);      //   - p1*S
                float t = __fadd_rn(W, B);           // W + B
                float c = __fmaf_rn(p2, G, np4);     // p2*G - p4
                float b = __fmaf_rn(np3, t, c);      //   - p3*(W+B)
                float d = __fmaf_rn(p5, S, np7);     // p5*S - p7
                d       = __fmaf_rn(np6, B, d);      //   - p6*B
                float e = __fmul_rn(W, d);           // W*(...)
                float f = __fadd_rn(S, W);           // S + W
                float g = __fmaf_rn(p8, f, np9);     // p8*(S+W) - p9
                float nB = __fmaf_rn(g, B, B);
                float nW = __fmaf_rn(e, W, W);
                float nS = __fmaf_rn(b, S, S);
                float nG = __fmaf_rn(a, G, G);
                B = nB; W = nW; S = nS; G = nG;
                traj[j] = make_float4(B, W, S, G);   // STS.128 (imm offset)
            }
            __threadfence_block();
            s_progress = end;
        }
        __threadfence_block();
        s_progress = num_steps;  // covers j0 == num_steps
    } else if (wid != 4 && tid >= 32) {
        // ------- consumers: warps 1,2,3,5,6,7 (SMSP 0 kept clear) --------
        const int ct  = (wid < 4) ? (tid - 32) : (tid - 64);  // 0..191
        const int ncs = 192;
        const float* tf = (const float*)traj;       // flat smem floats
        float4* o4 = (float4*)out;

        const int total_f  = num_steps * 5;
        const int total_f4 = total_f >> 2;
        const int n_chunks = (num_steps + CHUNK - 1) >> CHUNK_LOG2;
        const int f4_per_chunk = (CHUNK * 5) >> 2;  // 2560

        for (int k = 0; k < n_chunks; ++k) {
            const int rows_done = min((k + 1) << CHUNK_LOG2, num_steps);
            while (s_progress < rows_done) __nanosleep(1024);
            __threadfence_block();  // acquire: traj data before flag

            const int m0 = k * f4_per_chunk;
            const int m1 = min(m0 + f4_per_chunk, total_f4);
            for (int m = m0 + ct; m < m1; m += ncs) {
                const int n = m << 2;
                float v[4];
                #pragma unroll
                for (int e = 0; e < 4; ++e) {
                    const int ne = n + e;
                    const int r  = ne / 5;
                    const int c  = ne - r * 5;
                    v[e] = (c == 4) ? iv : tf[(r << 2) + c];
                }
                o4[m] = make_float4(v[0], v[1], v[2], v[3]);  // STG.128
            }
        }
        // scalar tail if num_steps*5 % 4 != 0 (not hit at 8192, kept general)
        if (ct == 0) {
            for (int ne = total_f4 << 2; ne < total_f; ++ne) {
                const int r = ne / 5;
                const int c = ne - r * 5;
                out[ne] = (c == 4) ? iv : tf[(r << 2) + c];
            }
        }
    }
    // warp 0 lanes 1..31 and all of warp 4: fall through and exit,
    // leaving SMSP 0's issue slots to the producer.
}

extern "C" void kernel_launch(void* const* d_in, const int* in_sizes, int n_in,
                              void* d_out, int out_size) {
    const float* y0     = (const float*)d_in[0];
    const float* params = (const float*)d_in[1];
    const int num_steps = out_size / 5;

    const size_t smem = (size_t)num_steps * sizeof(float4);
    cudaFuncSetAttribute(bwsg_ode_kernel,
                         cudaFuncAttributeMaxDynamicSharedMemorySize,
                         (int)smem);
    bwsg_ode_kernel<<<1, 256, smem>>>(y0, params, (float*)d_out, num_steps);
}

// round 16
// speedup vs baseline: 1.0091x; 1.0091x over previous
#include <cuda_runtime.h>

// BWSGODE: 8192-step serial scalar ODE — issue-bound single-thread loop.
//
// v16 = v14 (best, 101.3us; CHUNK 1024, unroll 128, 256ns poll) + fine-
// grained publishing of the FINAL 1024 rows in 256-row steps (64ns poll in
// the fine region). r15 taught: publish granularity trades producer fence
// cost (tiny) vs unhidden end-tail (dominant) — CHUNK 2048 lost 2us to the
// tail. This shrinks the tail instead: ~320 f4 + 64ns vs ~1280 f4 + 256ns.
// Certified model (r12-r14): 12 fma-port multiplies x rt2 = 24 cyc/iter
// floor; v14 measured 24.2. Structure locked since r7: thread 0 produces
// into shared traj, publishes via fence + volatile store; warps
// 1,2,3,5,6,7 stream chunks to global as STG.128; warp 4 exits so SMSP 0
// is producer-only.

#define CHUNK_LOG2 10
#define CHUNK (1 << CHUNK_LOG2)
#define FINE_LOG2 8
#define FINE (1 << FINE_LOG2)

__shared__ volatile int s_progress;

// Shared boundary schedule: 1024-row steps up to fine_start
// (= max(0, num_steps-1024) rounded to a 1024 boundary by construction),
// then 256-row steps to num_steps. All boundaries are multiples of 256,
// so row*5/4 stays integral and chunk copies remain pure STG.128.
__device__ __forceinline__ int next_boundary(int cur, int num_steps,
                                             int fine_start) {
    if (cur < fine_start) {
        int nb = (cur & ~(CHUNK - 1)) + CHUNK;
        return (nb > fine_start) ? fine_start : nb;
    }
    int nb = (cur & ~(FINE - 1)) + FINE;
    return (nb > num_steps) ? num_steps : nb;
}

__global__ void __launch_bounds__(256, 1)
bwsg_ode_kernel(const float* __restrict__ y0,
                const float* __restrict__ p,
                float* __restrict__ out,
                int num_steps) {
    extern __shared__ float4 traj[];  // num_steps entries (128 KB @ 8192)

    const int tid = threadIdx.x;
    const int wid = tid >> 5;
    if (tid == 0) s_progress = 0;
    __syncthreads();  // the ONLY block-wide sync; everything after is P/C.

    const float iv = __ldg(&y0[4]);
    const int fine_start = (num_steps > CHUNK) ? (num_steps - CHUNK) : 0;

    if (tid == 0) {
        // ---------------- producer: the serial recurrence ----------------
        float B = __ldg(&y0[0]);
        float W = __ldg(&y0[1]);
        float S = __ldg(&y0[2]);
        float G = __ldg(&y0[3]);

        const float p0 = p[0], p2 = p[2], p5 = p[5], p8 = p[8];
        const float np1 = -p[1], np3 = -p[3], np4 = -p[4];
        const float np6 = -p[6], np7 = -p[7], np9 = -p[9];
        const float np0 = -p0;

        const float fi  = (iv != 0.0f) ? 1.0f : 0.0f;
        const float thr = __fsub_rn(__fadd_rn(5.0f, iv), 1.0f);

        // First integer step with mask==1 (j >= thr <=> j >= ceil(thr) for
        // integer j; fp compare of exact integers is exact).
        int j0 = 1;
        if (fi != 0.0f) {
            float ct = ceilf(thr);
            if (ct > 1.0f) {
                j0 = (ct >= (float)num_steps) ? num_steps : (int)ct;
            }
        }

        traj[0] = make_float4(B, W, S, G);

        // ---- Phase 1: mask == 0 (interventional only), B frozen ----
        for (int j = 1; j < j0; ++j) {
            float a = __fmaf_rn(np0, G, p0);
            a       = __fmaf_rn(np1, S, a);
            float c = __fmaf_rn(p2, G, np4);
            float b = __fmaf_rn(np3, W, c);
            float d = __fmaf_rn(p5, S, np7);
            float e = __fmul_rn(W, d);
            float nS = __fmaf_rn(b, S, S);
            float nW = __fmaf_rn(e, W, W);
            float nG = __fmaf_rn(a, G, G);
            W = nW; S = nS; G = nG;
            traj[j] = make_float4(B, W, S, G);
        }

        // ---- Phase 2: mask == 1 hot loop (12 fma-port + 2 alu ops) ----
        int j = j0;
        while (j < num_steps) {
            const int end = next_boundary(j, num_steps, fine_start);
            #pragma unroll 128
            for (; j < end; ++j) {
                float a = __fmaf_rn(np0, G, p0);     // p0 - p0*G
                a       = __fmaf_rn(np1, S, a);      //   - p1*S
                float t = __fadd_rn(W, B);           // W + B
                float c = __fmaf_rn(p2, G, np4);     // p2*G - p4
                float b = __fmaf_rn(np3, t, c);      //   - p3*(W+B)
                float d = __fmaf_rn(p5, S, np7);     // p5*S - p7
                d       = __fmaf_rn(np6, B, d);      //   - p6*B
                float e = __fmul_rn(W, d);           // W*(...)
                float f = __fadd_rn(S, W);           // S + W
                float g = __fmaf_rn(p8, f, np9);     // p8*(S+W) - p9
                float nB = __fmaf_rn(g, B, B);
                float nW = __fmaf_rn(e, W, W);
                float nS = __fmaf_rn(b, S, S);
                float nG = __fmaf_rn(a, G, G);
                B = nB; W = nW; S = nS; G = nG;
                traj[j] = make_float4(B, W, S, G);   // STS.128 (imm offset)
            }
            __threadfence_block();
            s_progress = end;
        }
        __threadfence_block();
        s_progress = num_steps;  // covers j0 == num_steps
    } else if (wid != 4 && tid >= 32) {
        // ------- consumers: warps 1,2,3,5,6,7 (SMSP 0 kept clear) --------
        const int ct  = (wid < 4) ? (tid - 32) : (tid - 64);  // 0..191
        const int ncs = 192;
        const float* tf = (const float*)traj;       // flat smem floats
        float4* o4 = (float4*)out;

        const int total_f  = num_steps * 5;
        const int total_f4 = total_f >> 2;

        int b = 0;
        while (b < num_steps) {
            const int nb = next_boundary(b, num_steps, fine_start);
            const int slp = (nb > fine_start) ? 64 : 256;
            while (s_progress < nb) __nanosleep(slp);
            __threadfence_block();  // acquire: traj data before flag

            const int m0 = (b * 5) >> 2;   // b is a multiple of 256
            int m1 = (nb * 5) >> 2;
            if (m1 > total_f4) m1 = total_f4;
            for (int m = m0 + ct; m < m1; m += ncs) {
                const int n = m << 2;
                float v[4];
                #pragma unroll
                for (int e = 0; e < 4; ++e) {
                    const int ne = n + e;
                    const int r  = ne / 5;
                    const int c  = ne - r * 5;
                    v[e] = (c == 4) ? iv : tf[(r << 2) + c];
                }
                o4[m] = make_float4(v[0], v[1], v[2], v[3]);  // STG.128
            }
            b = nb;
        }
        // scalar tail if num_steps*5 % 4 != 0 (not hit at 8192, kept general)
        if (ct == 0) {
            for (int ne = total_f4 << 2; ne < total_f; ++ne) {
                const int r = ne / 5;
                const int c = ne - r * 5;
                out[ne] = (c == 4) ? iv : tf[(r << 2) + c];
            }
        }
    }
    // warp 0 lanes 1..31 and all of warp 4: fall through and exit,
    // leaving SMSP 0's issue slots to the producer.
}

extern "C" void kernel_launch(void* const* d_in, const int* in_sizes, int n_in,
                              void* d_out, int out_size) {
    const float* y0     = (const float*)d_in[0];
    const float* params = (const float*)d_in[1];
    const int num_steps = out_size / 5;

    const size_t smem = (size_t)num_steps * sizeof(float4);
    cudaFuncSetAttribute(bwsg_ode_kernel,
                         cudaFuncAttributeMaxDynamicSharedMemorySize,
                         (int)smem);
    bwsg_ode_kernel<<<1, 256, smem>>>(y0, params, (float*)d_out, num_steps);
}

// round 17
// speedup vs baseline: 1.0206x; 1.0114x over previous
#include <cuda_runtime.h>

// BWSGODE: 8192-step serial scalar ODE — final kernel (v17 = v14 verbatim).
//
// Certified performance model (rounds 2-16):
//   - The recurrence body is 12 fp32 multiplies/FMAs (fma port, rt=2/SMSP)
//     + 2 FADDs (alu pipe) + STS.128 (LSU) per step. The 12 products are
//     irreducible: each carries a runtime operand; every sharing rewrite
//     (W^2 tracking, multiplicative forms, constant folding) adds ops.
//   - Single-warp issue floor: 12 x 2 = 24 cyc/iter. Measured: 24.2.
//   - Killed: f32x2 packing (r3/r4), FFMA-imm (r5), store splitting (r9),
//     release/acquire publish (r10), coarser/finer publish (r15/r16 — the
//     tail and fences are fully hidden), fp64/MUFU offload (latency),
//     lane-split & cross-warp splitting (SHFL/LDS in the carried chain),
//     fp16 (precision), tensor cores (state-dependent coefficients).
//   - Unroll 128 amortizes BRA/bookkeeping to <0.2 cyc/iter; body ~30KB
//     fits the 32KB L1.5 I$ (unroll 256 would not).
//   - Warps 1,2,3,5,6,7 stream published 1024-row chunks to global as
//     STG.128; warp 4 exits so SMSP 0 belongs to the producer alone
//     (hi-wid-first arbiter; r7: -4.2us).
// rel_err canary: 2.224576e-06 (bit-stable since r2).

#define CHUNK_LOG2 10
#define CHUNK (1 << CHUNK_LOG2)

__shared__ volatile int s_progress;

__global__ void __launch_bounds__(256, 1)
bwsg_ode_kernel(const float* __restrict__ y0,
                const float* __restrict__ p,
                float* __restrict__ out,
                int num_steps) {
    extern __shared__ float4 traj[];  // num_steps entries (128 KB @ 8192)

    const int tid = threadIdx.x;
    const int wid = tid >> 5;
    if (tid == 0) s_progress = 0;
    __syncthreads();  // the ONLY block-wide sync; everything after is P/C.

    const float iv = __ldg(&y0[4]);

    if (tid == 0) {
        // ---------------- producer: the serial recurrence ----------------
        float B = __ldg(&y0[0]);
        float W = __ldg(&y0[1]);
        float S = __ldg(&y0[2]);
        float G = __ldg(&y0[3]);

        const float p0 = p[0], p2 = p[2], p5 = p[5], p8 = p[8];
        const float np1 = -p[1], np3 = -p[3], np4 = -p[4];
        const float np6 = -p[6], np7 = -p[7], np9 = -p[9];
        const float np0 = -p0;

        const float fi  = (iv != 0.0f) ? 1.0f : 0.0f;
        const float thr = __fsub_rn(__fadd_rn(5.0f, iv), 1.0f);

        // First integer step with mask==1 (j >= thr <=> j >= ceil(thr) for
        // integer j; fp compare of exact integers is exact).
        int j0 = 1;
        if (fi != 0.0f) {
            float ct = ceilf(thr);
            if (ct > 1.0f) {
                j0 = (ct >= (float)num_steps) ? num_steps : (int)ct;
            }
        }

        traj[0] = make_float4(B, W, S, G);

        // ---- Phase 1: mask == 0 (interventional only), B frozen ----
        for (int j = 1; j < j0; ++j) {
            float a = __fmaf_rn(np0, G, p0);
            a       = __fmaf_rn(np1, S, a);
            float c = __fmaf_rn(p2, G, np4);
            float b = __fmaf_rn(np3, W, c);
            float d = __fmaf_rn(p5, S, np7);
            float e = __fmul_rn(W, d);
            float nS = __fmaf_rn(b, S, S);
            float nW = __fmaf_rn(e, W, W);
            float nG = __fmaf_rn(a, G, G);
            W = nW; S = nS; G = nG;
            traj[j] = make_float4(B, W, S, G);
        }

        // ---- Phase 2: mask == 1 hot loop (12 fma-port + 2 alu ops) ----
        int j = j0;
        while (j < num_steps) {
            const int end = min((((j >> CHUNK_LOG2) + 1) << CHUNK_LOG2),
                                num_steps);
            #pragma unroll 128
            for (; j < end; ++j) {
                float a = __fmaf_rn(np0, G, p0);     // p0 - p0*G
                a       = __fmaf_rn(np1, S, a);      //   - p1*S
                float t = __fadd_rn(W, B);           // W + B   (alu pipe)
                float c = __fmaf_rn(p2, G, np4);     // p2*G - p4
                float b = __fmaf_rn(np3, t, c);      //   - p3*(W+B)
                float d = __fmaf_rn(p5, S, np7);     // p5*S - p7
                d       = __fmaf_rn(np6, B, d);      //   - p6*B
                float e = __fmul_rn(W, d);           // W*(...)
                float f = __fadd_rn(S, W);           // S + W   (alu pipe)
                float g = __fmaf_rn(p8, f, np9);     // p8*(S+W) - p9
                float nB = __fmaf_rn(g, B, B);
                float nW = __fmaf_rn(e, W, W);
                float nS = __fmaf_rn(b, S, S);
                float nG = __fmaf_rn(a, G, G);
                B = nB; W = nW; S = nS; G = nG;
                traj[j] = make_float4(B, W, S, G);   // STS.128 (imm offset)
            }
            __threadfence_block();
            s_progress = end;
        }
        __threadfence_block();
        s_progress = num_steps;  // covers j0 == num_steps
    } else if (wid != 4 && tid >= 32) {
        // ------- consumers: warps 1,2,3,5,6,7 (SMSP 0 kept clear) --------
        const int ct  = (wid < 4) ? (tid - 32) : (tid - 64);  // 0..191
        const int ncs = 192;
        const float* tf = (const float*)traj;       // flat smem floats
        float4* o4 = (float4*)out;

        const int total_f  = num_steps * 5;
        const int total_f4 = total_f >> 2;
        const int n_chunks = (num_steps + CHUNK - 1) >> CHUNK_LOG2;
        const int f4_per_chunk = (CHUNK * 5) >> 2;  // 1280

        for (int k = 0; k < n_chunks; ++k) {
            const int rows_done = min((k + 1) << CHUNK_LOG2, num_steps);
            while (s_progress < rows_done) __nanosleep(256);
            __threadfence_block();  // acquire: traj data before flag

            const int m0 = k * f4_per_chunk;
            const int m1 = min(m0 + f4_per_chunk, total_f4);
            for (int m = m0 + ct; m < m1; m += ncs) {
                const int n = m << 2;
                float v[4];
                #pragma unroll
                for (int e = 0; e < 4; ++e) {
                    const int ne = n + e;
                    const int r  = ne / 5;
                    const int c  = ne - r * 5;
                    v[e] = (c == 4) ? iv : tf[(r << 2) + c];
                }
                o4[m] = make_float4(v[0], v[1], v[2], v[3]);  // STG.128
            }
        }
        // scalar tail if num_steps*5 % 4 != 0 (not hit at 8192, kept general)
        if (ct == 0) {
            for (int ne = total_f4 << 2; ne < total_f; ++ne) {
                const int r = ne / 5;
                const int c = ne - r * 5;
                out[ne] = (c == 4) ? iv : tf[(r << 2) + c];
            }
        }
    }
    // warp 0 lanes 1..31 and all of warp 4: fall through and exit,
    // leaving SMSP 0's issue slots to the producer.
}

extern "C" void kernel_launch(void* const* d_in, const int* in_sizes, int n_in,
                              void* d_out, int out_size) {
    const float* y0     = (const float*)d_in[0];
    const float* params = (const float*)d_in[1];
    const int num_steps = out_size / 5;

    const size_t smem = (size_t)num_steps * sizeof(float4);
    cudaFuncSetAttribute(bwsg_ode_kernel,
                         cudaFuncAttributeMaxDynamicSharedMemorySize,
                         (int)smem);
    bwsg_ode_kernel<<<1, 256, smem>>>(y0, params, (float*)d_out, num_steps);
}